// round 8
// baseline (speedup 1.0000x reference)
#include <cuda_runtime.h>
#include <cstdint>

#define NN 65536       // nodes (2*B*S)
#define EE 524288      // edges (2*B*EPG)
#define NG 512         // graphs, 128 nodes + 1024 edges each
#define NPAIR 256

// ---------------- device scratch (static: no cudaMalloc allowed) ----------------
__device__ __align__(256) float d_hs[(size_t)NN * 128];     // [:, :64]=h, [:,64:]=store
__device__ __align__(256) float d_g[(size_t)NN * 128];      // relu hidden of comb-MLP
__device__ __align__(256) float d_cR[(size_t)NN * 208];     // [:,0:64]=comb,[:,64:192]=agg,[:,192:208]=0
__device__ __align__(256) float d_pApB[(size_t)NN * 256];   // pA|pB, then R|deg|0pad (cols 0..143)
__device__ __align__(256) float d_uh[(size_t)NN * 128];     // relu hidden of u-MLP
__device__ __align__(256) float d_t[(size_t)NN * 32];
__device__ __align__(256) float d_pe[(size_t)EE * 128];     // per-edge bias (incl b_m1), iter-invariant
__device__ __align__(256) float d_eenc[(size_t)EE * 32];    // e_enc
__device__ unsigned d_eidx[EE];                             // packed local from|to
__device__ __align__(256) float d_Wm2e[144 * 128];          // [W_m2(128); b_m2(1); 0(15)]
__device__ __align__(256) float d_Wu1p[208 * 128];          // [W_u1(192); 0(16)]
__device__ __align__(256) float d_Wm1pack[64 * 256];        // [Wm1[0:64] | Wm1[64:128]] packed
__device__ int d_is64;

// ---------------- precise exp/log (fast-math-proof) ----------------
__device__ __forceinline__ float expp(float x) {
    x = fmaxf(x, -87.0f);
    float nf = rintf(x * 1.4426950408889634f);
    float r = fmaf(nf, -0.693145751953125f, x);     // ln2_hi
    r = fmaf(nf, -1.428606765330187e-6f, r);        // ln2_lo
    float p = 1.9841269841e-4f;
    p = fmaf(p, r, 1.3888888889e-3f);
    p = fmaf(p, r, 8.3333333333e-3f);
    p = fmaf(p, r, 4.1666666667e-2f);
    p = fmaf(p, r, 1.6666666667e-1f);
    p = fmaf(p, r, 0.5f);
    p = fmaf(p, r, 1.0f);
    p = fmaf(p, r, 1.0f);
    int n = (int)nf;
    return p * __int_as_float((n + 127) << 23);
}

__device__ __forceinline__ float logp(float x) {
    int i = __float_as_int(x);
    int e = (i - 0x3f3504f3) >> 23;
    float m = __int_as_float(i - (e << 23));
    float f = m - 1.0f;
    float s = __fdiv_rn(f, 2.0f + f);
    float s2 = s * s;
    float p = 0.2222222222f;
    p = fmaf(p, s2, 0.2857142857f);
    p = fmaf(p, s2, 0.4f);
    p = fmaf(p, s2, 0.6666666667f);
    p = fmaf(p, s2, 2.0f);
    float lm = s * p;
    float ef = (float)e;
    float r = fmaf(ef, 1.428606765330187e-6f, lm);
    r = fmaf(ef, 0.693145751953125f, r);
    return r;
}

// ---------------- index dtype detection + conversion ----------------
__global__ void detect_kernel(const unsigned* __restrict__ p) {
    if (threadIdx.x == 0) {
        int is64 = 1;
        for (int i = 1; i < 64; i += 2)
            if (p[i] != 0u) { is64 = 0; break; }
        d_is64 = is64;
    }
}

__global__ void convert_kernel(const void* __restrict__ fr, const void* __restrict__ to) {
    int e = blockIdx.x * 256 + threadIdx.x;
    if (e >= EE) return;
    int f, t;
    if (d_is64) {
        f = (int)((const long long*)fr)[e];
        t = (int)((const long long*)to)[e];
    } else {
        f = ((const int*)fr)[e];
        t = ((const int*)to)[e];
    }
    d_eidx[e] = (unsigned)(f & 127) | (((unsigned)(t & 127)) << 8);
}

// zero store-half of hs and pad columns of cR
__global__ void init_kernel() {
    int i = blockIdx.x * 256 + threadIdx.x;
    if (i < NN * 64) d_hs[((size_t)(i >> 6)) * 128 + 64 + (i & 63)] = 0.f;
    if (i < NN * 16) d_cR[((size_t)(i >> 4)) * 208 + 192 + (i & 15)] = 0.f;
}

// ---------------- weight padding/packing precompute (pure copies, exact) ----------------
__global__ void precompute_kernel(
    const float* __restrict__ Wm2, const float* __restrict__ bm2,
    const float* __restrict__ Wu1, const float* __restrict__ Wm1)
{
    int idx = blockIdx.x * 256 + threadIdx.x;
    if (idx < 144 * 128) {
        int r = idx >> 7, j = idx & 127;
        float v = 0.f;
        if (r < 128) v = Wm2[r * 128 + j];
        else if (r == 128) v = bm2[j];
        d_Wm2e[idx] = v;
        return;
    }
    idx -= 144 * 128;
    if (idx < 208 * 128) {
        int r = idx >> 7;
        d_Wu1p[idx] = (r < 192) ? Wu1[idx] : 0.f;
        return;
    }
    idx -= 208 * 128;
    if (idx < 64 * 256) {
        int k = idx >> 8, j = idx & 255;
        d_Wm1pack[idx] = (j < 128) ? Wm1[k * 128 + j] : Wm1[(64 + k) * 128 + (j - 128)];
    }
}

// ---------------- eenc: e_enc = edge_f(Ex8) @ W_enc_e(8x32) + b, ascending-k ----------------
__global__ void __launch_bounds__(256) eenc_kernel(
    const float* __restrict__ ef, const float* __restrict__ W, const float* __restrict__ b)
{
    __shared__ float sW[8 * 32], sb[32], sf[64 * 8];
    const int tid = threadIdx.x;
    if (tid < 256) sW[tid] = W[tid];
    if (tid < 32) sb[tid] = b[tid];
    const size_t base = (size_t)blockIdx.x * 64;
    if (tid < 128) ((float4*)sf)[tid] = ((const float4*)(ef + base * 8))[tid];
    __syncthreads();

    const int e_loc = tid >> 2;
    const int jq = (tid & 3) * 8;
    float f[8];
#pragma unroll
    for (int k = 0; k < 8; k++) f[k] = sf[e_loc * 8 + k];
    float o[8];
#pragma unroll
    for (int j = 0; j < 8; j++) {
        float s = 0.f;
#pragma unroll
        for (int k = 0; k < 8; k++) s += f[k] * sW[k * 32 + jq + j];
        o[j] = s + sb[jq + j];
    }
    float* dst = d_eenc + (base + e_loc) * 32 + jq;
    *(float4*)dst = make_float4(o[0], o[1], o[2], o[3]);
    *(float4*)(dst + 4) = make_float4(o[4], o[5], o[6], o[7]);
}

// ---------------- SGEMM16: 16-deep double-buffered tiles, BN in {128, 64} ----------------
// C = [relu](A(rows x K) @ B(K x M) + bias); rows mult 128, K mult 16, lda/ldb/ldc/M mult 4.
template<int BN>
__global__ void __launch_bounds__(256) sgemm16_kernel(
    const float* __restrict__ A, int lda,
    const float* __restrict__ B, int ldb,
    float* __restrict__ C, int ldc,
    const float* __restrict__ bias,
    int K, int M, int doRelu)
{
    __shared__ __align__(16) float As[2][16][128];
    __shared__ __align__(16) float Bs[2][16][BN];
    const int tid = threadIdx.x;
    const int tx = tid & 15, ty = tid >> 4;
    const int brow = blockIdx.y << 7;
    const int bcol = blockIdx.x * BN;
    // A loader: thread covers row aRow, k-chunks {aK0, aK0+8}
    const int aRow = tid >> 1;
    const int aK0 = (tid & 1) << 2;
    // B loader
    const int bK  = (BN == 128) ? (tid >> 5) : (tid >> 4);
    const int bC  = (BN == 128) ? ((tid & 31) << 2) : ((tid & 15) << 2);
    const int bc  = bcol + bC;

    constexpr int NJ = (BN == 128) ? 8 : 4;
    float acc[8][NJ];
#pragma unroll
    for (int i = 0; i < 8; i++)
#pragma unroll
        for (int j = 0; j < NJ; j++) acc[i][j] = 0.f;

    // prologue: tile 0
    {
        const float* Ap = A + (size_t)(brow + aRow) * lda;
        float4 a0 = *(const float4*)(Ap + aK0);
        float4 a1 = *(const float4*)(Ap + aK0 + 8);
        As[0][aK0 + 0][aRow] = a0.x; As[0][aK0 + 1][aRow] = a0.y;
        As[0][aK0 + 2][aRow] = a0.z; As[0][aK0 + 3][aRow] = a0.w;
        As[0][aK0 + 8][aRow] = a1.x; As[0][aK0 + 9][aRow] = a1.y;
        As[0][aK0 +10][aRow] = a1.z; As[0][aK0 +11][aRow] = a1.w;
        float4 b0 = make_float4(0.f,0.f,0.f,0.f), b1 = make_float4(0.f,0.f,0.f,0.f);
        if (bc < M) {
            b0 = *(const float4*)(B + (size_t)bK * ldb + bc);
            if (BN == 128) b1 = *(const float4*)(B + (size_t)(bK + 8) * ldb + bc);
        }
        *(float4*)&Bs[0][bK][bC] = b0;
        if (BN == 128) *(float4*)&Bs[0][bK + 8][bC] = b1;
    }
    __syncthreads();

    const int nk = K >> 4;
    int buf = 0;
    for (int t = 0; t < nk; t++) {
        float4 pa0, pa1, pb0, pb1;
        const bool more = (t + 1 < nk);
        if (more) {
            int k0 = (t + 1) << 4;
            const float* Ap = A + (size_t)(brow + aRow) * lda + k0;
            pa0 = *(const float4*)(Ap + aK0);
            pa1 = *(const float4*)(Ap + aK0 + 8);
            pb0 = make_float4(0.f,0.f,0.f,0.f); pb1 = make_float4(0.f,0.f,0.f,0.f);
            if (bc < M) {
                pb0 = *(const float4*)(B + (size_t)(k0 + bK) * ldb + bc);
                if (BN == 128) pb1 = *(const float4*)(B + (size_t)(k0 + bK + 8) * ldb + bc);
            }
        }
#pragma unroll
        for (int kk = 0; kk < 16; kk++) {
            float4 a0 = *(const float4*)&As[buf][kk][ty * 4];
            float4 a1 = *(const float4*)&As[buf][kk][64 + ty * 4];
            float a[8] = {a0.x,a0.y,a0.z,a0.w,a1.x,a1.y,a1.z,a1.w};
            float4 b0 = *(const float4*)&Bs[buf][kk][tx * 4];
            float b[NJ];
            b[0]=b0.x; b[1]=b0.y; b[2]=b0.z; b[3]=b0.w;
            if (BN == 128) {
                float4 b1 = *(const float4*)&Bs[buf][kk][64 + tx * 4];
                b[4]=b1.x; b[5]=b1.y; b[6]=b1.z; b[7]=b1.w;
            }
#pragma unroll
            for (int i = 0; i < 8; i++)
#pragma unroll
                for (int j = 0; j < NJ; j++) acc[i][j] += a[i] * b[j];
        }
        if (more) {
            int nb = buf ^ 1;
            As[nb][aK0 + 0][aRow] = pa0.x; As[nb][aK0 + 1][aRow] = pa0.y;
            As[nb][aK0 + 2][aRow] = pa0.z; As[nb][aK0 + 3][aRow] = pa0.w;
            As[nb][aK0 + 8][aRow] = pa1.x; As[nb][aK0 + 9][aRow] = pa1.y;
            As[nb][aK0 +10][aRow] = pa1.z; As[nb][aK0 +11][aRow] = pa1.w;
            *(float4*)&Bs[nb][bK][bC] = pb0;
            if (BN == 128) *(float4*)&Bs[nb][bK + 8][bC] = pb1;
            __syncthreads();
            buf = nb;
        }
    }

#pragma unroll
    for (int ri = 0; ri < 2; ri++) {
#pragma unroll
        for (int i = 0; i < 4; i++) {
            int row = brow + ri * 64 + ty * 4 + i;
            int ai = ri * 4 + i;
#pragma unroll
            for (int cj = 0; cj < NJ / 4; cj++) {
                int col = bcol + cj * 64 + tx * 4;
                if (col < M) {
                    int aj = cj * 4;
                    float4 v = make_float4(acc[ai][aj], acc[ai][aj+1], acc[ai][aj+2], acc[ai][aj+3]);
                    if (bias) {
                        v.x += bias[col]; v.y += bias[col+1];
                        v.z += bias[col+2]; v.w += bias[col+3];
                    }
                    if (doRelu) {
                        v.x = fmaxf(v.x, 0.f); v.y = fmaxf(v.y, 0.f);
                        v.z = fmaxf(v.z, 0.f); v.w = fmaxf(v.w, 0.f);
                    }
                    *(float4*)(C + (size_t)row * ldc + col) = v;
                }
            }
        }
    }
}

// ---------------- fused t-MLP ----------------
__global__ void __launch_bounds__(256) tmlp_kernel(
    const float* __restrict__ Wt1, const float* __restrict__ bt1,
    const float* __restrict__ Wt2, const float* __restrict__ bt2)
{
    __shared__ float sW1[64 * 32], sW2[32 * 32], sb1[32], sb2[32];
    const int tid = threadIdx.x;
    for (int i = tid; i < 64 * 32; i += 256) sW1[i] = Wt1[i];
    for (int i = tid; i < 32 * 32; i += 256) sW2[i] = Wt2[i];
    if (tid < 32) { sb1[tid] = bt1[tid]; sb2[tid] = bt2[tid]; }
    __syncthreads();

    const size_t row = (size_t)blockIdx.x * 256 + tid;
    float h[64];
    const float4* hp = (const float4*)&d_hs[row * 128];
#pragma unroll
    for (int q = 0; q < 16; q++) {
        float4 v = hp[q];
        h[q*4+0] = v.x; h[q*4+1] = v.y; h[q*4+2] = v.z; h[q*4+3] = v.w;
    }
    float th[32];
#pragma unroll
    for (int j = 0; j < 32; j++) {
        float s = 0.f;
        for (int k = 0; k < 64; k++) s += h[k] * sW1[k * 32 + j];
        th[j] = fmaxf(s + sb1[j], 0.f);
    }
#pragma unroll
    for (int j = 0; j < 32; j++) {
        float s = 0.f;
        for (int k = 0; k < 32; k++) s += th[k] * sW2[k * 32 + j];
        d_t[row * 32 + j] = s + sb2[j];
    }
}

// ---------------- per-graph edge message + aggregate ----------------
__global__ void __launch_bounds__(128) edge_kernel() {
    extern __shared__ float sm[];
    float* sP = sm;                       // 128*256
    float* sR = sm + 128 * 256;           // 128*128
    unsigned* se = (unsigned*)(sR + 128 * 128);  // 1024
    int* sdeg = (int*)(se + 1024);        // 128
    const int g = blockIdx.x;
    const int j = threadIdx.x;

    float* gp = d_pApB + (size_t)g * 128 * 256;
    for (int i = j; i < 128 * 256 / 4; i += 128)
        ((float4*)sP)[i] = ((const float4*)gp)[i];
    for (int i = j; i < 128 * 128 / 4; i += 128)
        ((float4*)sR)[i] = make_float4(0.f, 0.f, 0.f, 0.f);
    for (int e = j; e < 1024; e += 128) se[e] = d_eidx[g * 1024 + e];
    sdeg[j] = 0;
    __syncthreads();

    for (int e = j; e < 1024; e += 128) {
        unsigned v = se[e];
        atomicAdd(&sdeg[v & 255], 1);
        atomicAdd(&sdeg[(v >> 8) & 255], 1);
    }

    const float* peg = d_pe + ((size_t)g * 1024) * 128 + j;
    float pa[8], pb[8];
#pragma unroll
    for (int u = 0; u < 8; u++) pa[u] = peg[(size_t)u * 128];

    for (int eb = 0; eb < 1024; eb += 8) {
        if (eb + 8 < 1024) {
#pragma unroll
            for (int u = 0; u < 8; u++) pb[u] = peg[(size_t)(eb + 8 + u) * 128];
        }
#pragma unroll
        for (int u = 0; u < 8; u++) {
            unsigned v = se[eb + u];
            int f = v & 255, t = (v >> 8) & 255;
            float p = pa[u];
            float zf = sP[f * 256 + j] + sP[t * 256 + 128 + j] + p;
            float zr = sP[t * 256 + j] + sP[f * 256 + 128 + j] + p;
            sR[t * 128 + j] += fmaxf(zf, 0.f);
            sR[f * 128 + j] += fmaxf(zr, 0.f);
        }
#pragma unroll
        for (int u = 0; u < 8; u++) pa[u] = pb[u];
    }
    __syncthreads();
    for (int r = 0; r < 128; r++)
        gp[(size_t)r * 256 + j] = sR[r * 128 + j];
    if (j < 16) {
        for (int r = 0; r < 128; r++)
            gp[(size_t)r * 256 + 128 + j] = (j == 0) ? (float)sdeg[r] : 0.f;
    }
}

// ---------------- per-pair: 101 KB smem, 2 CTAs/SM, phased buffer reuse ----------------
__global__ void __launch_bounds__(256, 2) pair_kernel(float* __restrict__ out) {
    extern __shared__ float sm[];
    float* A   = sm;                // 128*129 = 16512
    float* buf = A + 16512;         // 8192
    float* pm  = buf + 8192;        // 256
    float* ps  = pm + 256;          // 256
    float* f   = ps + 256;          // 128
    const int p = blockIdx.x;
    const int tid = threadIdx.x;
    const int r = tid & 127;
    const int half = tid >> 7;
    const int c0 = half << 6;
    const size_t qbase = (size_t)(2 * p) * 128;
    const size_t cbase = (size_t)(2 * p + 1) * 128;

    float tq[32];
#pragma unroll
    for (int k = 0; k < 32; k++) tq[k] = d_t[(qbase + r) * 32 + k];
    for (int idx = tid; idx < 128 * 32 / 4; idx += 256)
        ((float4*)buf)[idx] = ((const float4*)(d_t + cbase * 32))[idx];
    __syncthreads();

    for (int jj = c0; jj < c0 + 64; jj++) {
        float s = 0.f;
        const float4* tc4 = (const float4*)(buf + jj * 32);
#pragma unroll
        for (int q = 0; q < 8; q++) {
            float4 cv = tc4[q];
            s += tq[q*4+0] * cv.x; s += tq[q*4+1] * cv.y;
            s += tq[q*4+2] * cv.z; s += tq[q*4+3] * cv.w;
        }
        A[r * 129 + jj] = __fdiv_rn(s, 0.1f);
    }
    __syncthreads();

    for (int it = 0; it < 20; it++) {
        float m = -1e30f;
        for (int jj = c0; jj < c0 + 64; jj++) m = fmaxf(m, A[r * 129 + jj]);
        pm[half * 128 + r] = m;
        __syncthreads();
        float M2 = fmaxf(pm[r], pm[128 + r]);
        float s = 0.f;
        for (int jj = c0; jj < c0 + 64; jj++) s += expp(A[r * 129 + jj] - M2);
        ps[half * 128 + r] = s;
        __syncthreads();
        float l = M2 + logp(ps[r] + ps[128 + r]);
        for (int jj = c0; jj < c0 + 64; jj++) A[r * 129 + jj] -= l;
        __syncthreads();
        m = -1e30f;
        for (int ii = c0; ii < c0 + 64; ii++) m = fmaxf(m, A[ii * 129 + r]);
        pm[half * 128 + r] = m;
        __syncthreads();
        M2 = fmaxf(pm[r], pm[128 + r]);
        s = 0.f;
        for (int ii = c0; ii < c0 + 64; ii++) s += expp(A[ii * 129 + r] - M2);
        ps[half * 128 + r] = s;
        __syncthreads();
        l = M2 + logp(ps[r] + ps[128 + r]);
        for (int ii = c0; ii < c0 + 64; ii++) A[ii * 129 + r] -= l;
        __syncthreads();
    }

    for (int jj = c0; jj < c0 + 64; jj++)
        A[r * 129 + jj] = expp(A[r * 129 + jj]);
    for (int idx = tid; idx < 128 * 64 / 4; idx += 256) {
        int rr = idx >> 4, c4 = (idx & 15) << 2;
        ((float4*)buf)[idx] = *(const float4*)&d_hs[(cbase + rr) * 128 + c4];
    }
    __syncthreads();

    const int d0 = half << 5;
    float acc[32];
#pragma unroll
    for (int d = 0; d < 32; d++) acc[d] = 0.f;
    for (int jj = 0; jj < 128; jj++) {
        float t = A[r * 129 + jj];
        const float4* cv4 = (const float4*)(buf + jj * 64 + d0);
#pragma unroll
        for (int q = 0; q < 8; q++) {
            float4 cv = cv4[q];
            acc[q*4+0] += t * cv.x; acc[q*4+1] += t * cv.y;
            acc[q*4+2] += t * cv.z; acc[q*4+3] += t * cv.w;
        }
    }
    float sloc = 0.f;
    {
        const float4* qp = (const float4*)&d_hs[(qbase + r) * 128 + d0];
#pragma unroll
        for (int q8 = 0; q8 < 8; q8++) {
            float4 qv = qp[q8];
            sloc += fmaxf(qv.x - acc[q8*4+0], 0.f);
            sloc += fmaxf(qv.y - acc[q8*4+1], 0.f);
            sloc += fmaxf(qv.z - acc[q8*4+2], 0.f);
            sloc += fmaxf(qv.w - acc[q8*4+3], 0.f);
        }
    }
#pragma unroll
    for (int d = 0; d < 32; d++)
        d_hs[(qbase + r) * 128 + 64 + d0 + d] = acc[d];
    ps[half * 128 + r] = sloc;
    __syncthreads();

    for (int idx = tid; idx < 128 * 64 / 4; idx += 256) {
        int rr = idx >> 4, c4 = (idx & 15) << 2;
        ((float4*)buf)[idx] = *(const float4*)&d_hs[(qbase + rr) * 128 + c4];
    }
    if (tid < 128) f[tid] = ps[tid] + ps[128 + tid];
    __syncthreads();

    if (tid < 32) {
        float v = f[tid] + f[tid + 32] + f[tid + 64] + f[tid + 96];
#pragma unroll
        for (int o = 16; o; o >>= 1) v += __shfl_down_sync(0xffffffffu, v, o);
        if (tid == 0) out[p] = -v;
    }

#pragma unroll
    for (int d = 0; d < 32; d++) acc[d] = 0.f;
    for (int ii = 0; ii < 128; ii++) {
        float t = A[ii * 129 + r];
        const float4* qv4 = (const float4*)(buf + ii * 64 + d0);
#pragma unroll
        for (int q = 0; q < 8; q++) {
            float4 qv = qv4[q];
            acc[q*4+0] += t * qv.x; acc[q*4+1] += t * qv.y;
            acc[q*4+2] += t * qv.z; acc[q*4+3] += t * qv.w;
        }
    }
#pragma unroll
    for (int d = 0; d < 32; d++)
        d_hs[(cbase + r) * 128 + 64 + d0 + d] = acc[d];
}

// ---------------- launcher ----------------
static void run_sgemm(const float* A, int lda, const float* B, int ldb,
                      float* C, int ldc, const float* bias,
                      int rows, int K, int M, int relu) {
    if (M <= 64) {
        dim3 grid(1, rows / 128);
        sgemm16_kernel<64><<<grid, 256>>>(A, lda, B, ldb, C, ldc, bias, K, M, relu);
    } else {
        dim3 grid((M + 127) / 128, rows / 128);
        sgemm16_kernel<128><<<grid, 256>>>(A, lda, B, ldb, C, ldc, bias, K, M, relu);
    }
}

extern "C" void kernel_launch(void* const* d_in, const int* in_sizes, int n_in,
                              void* d_out, int out_size) {
    const float* node_f = (const float*)d_in[0];
    const float* edge_f = (const float*)d_in[1];
    const float* W_enc_n = (const float*)d_in[2];
    const float* b_enc_n = (const float*)d_in[3];
    const float* W_enc_e = (const float*)d_in[4];
    const float* b_enc_e = (const float*)d_in[5];
    const float* W_c1 = (const float*)d_in[6];
    const float* b_c1 = (const float*)d_in[7];
    const float* W_c2 = (const float*)d_in[8];
    const float* b_c2 = (const float*)d_in[9];
    const float* W_m1 = (const float*)d_in[10];
    const float* b_m1 = (const float*)d_in[11];
    const float* W_m2 = (const float*)d_in[12];
    const float* b_m2 = (const float*)d_in[13];
    const float* W_u1 = (const float*)d_in[14];
    const float* b_u1 = (const float*)d_in[15];
    const float* W_u2 = (const float*)d_in[16];
    const float* b_u2 = (const float*)d_in[17];
    const float* W_t1 = (const float*)d_in[18];
    const float* b_t1 = (const float*)d_in[19];
    const float* W_t2 = (const float*)d_in[20];
    const float* b_t2 = (const float*)d_in[21];
    const void* from_idx = d_in[22];
    const void* to_idx = d_in[23];
    float* out = (float*)d_out;

    static const int SMEM_EDGE = (128 * 256 + 128 * 128) * 4 + 1024 * 4 + 128 * 4; // 201216
    static const int SMEM_PAIR = (16512 + 8192 + 256 + 256 + 128) * 4;             // 101376
    cudaFuncSetAttribute(edge_kernel, cudaFuncAttributeMaxDynamicSharedMemorySize, SMEM_EDGE);
    cudaFuncSetAttribute(pair_kernel, cudaFuncAttributeMaxDynamicSharedMemorySize, SMEM_PAIR);

    float* hs; cudaGetSymbolAddress((void**)&hs, d_hs);
    float* gbuf; cudaGetSymbolAddress((void**)&gbuf, d_g);
    float* cR; cudaGetSymbolAddress((void**)&cR, d_cR);
    float* pApB; cudaGetSymbolAddress((void**)&pApB, d_pApB);
    float* uh; cudaGetSymbolAddress((void**)&uh, d_uh);
    float* pe; cudaGetSymbolAddress((void**)&pe, d_pe);
    float* eenc; cudaGetSymbolAddress((void**)&eenc, d_eenc);
    float* Wm2e; cudaGetSymbolAddress((void**)&Wm2e, d_Wm2e);
    float* Wu1p; cudaGetSymbolAddress((void**)&Wu1p, d_Wu1p);
    float* Wm1pack; cudaGetSymbolAddress((void**)&Wm1pack, d_Wm1pack);

    // setup — pe SGEMM stays at launch index 3 (profiled)
    detect_kernel<<<1, 32>>>((const unsigned*)from_idx);                         // 0
    convert_kernel<<<EE / 256, 256>>>(from_idx, to_idx);                         // 1
    eenc_kernel<<<EE / 64, 256>>>(edge_f, W_enc_e, b_enc_e);                     // 2
    run_sgemm(eenc, 32, W_m1 + 128 * 128, 128, pe, 128, b_m1, EE, 32, 128, 0);   // 3
    init_kernel<<<(NN * 64) / 256, 256>>>();                                     // 4
    precompute_kernel<<<(144 * 128 + 208 * 128 + 64 * 256 + 255) / 256, 256>>>(
        W_m2, b_m2, W_u1, W_m1);                                                 // 5
    run_sgemm(node_f, 16, W_enc_n, 64, hs, 128, b_enc_n, NN, 16, 64, 0);         // 6

    for (int iter = 0; iter < 5; iter++) {
        // g = relu([h|store] @ W_c1 + b_c1)
        run_sgemm(hs, 128, W_c1, 128, gbuf, 128, b_c1, NN, 128, 128, 1);
        // comb = g @ W_c2 + b_c2  -> cR[:, 0:64]
        run_sgemm(gbuf, 128, W_c2, 64, cR, 208, b_c2, NN, 128, 64, 0);
        // pA|pB = comb @ Wm1pack  (M=256)
        run_sgemm(cR, 208, Wm1pack, 256, pApB, 256, nullptr, NN, 64, 256, 0);
        // R|deg|0 -> pApB cols 0..143
        edge_kernel<<<NG, 128, SMEM_EDGE>>>();
        // agg = [R|deg|0] @ Wm2e -> cR[:, 64:192]
        run_sgemm(pApB, 256, Wm2e, 128, cR + 64, 208, nullptr, NN, 144, 128, 0);
        // uh = relu([comb|agg|0] @ Wu1p + b_u1)
        run_sgemm(cR, 208, Wu1p, 128, uh, 128, b_u1, NN, 208, 128, 1);
        // h = uh @ W_u2 + b_u2 -> hs[:, :64]
        run_sgemm(uh, 128, W_u2, 64, hs, 128, b_u2, NN, 128, 64, 0);
        // t = relu(h @ W_t1 + b_t1) @ W_t2 + b_t2 (fused)
        tmlp_kernel<<<NN / 256, 256>>>(W_t1, b_t1, W_t2, b_t2);
        // sinkhorn + transports + store + scores
        pair_kernel<<<NPAIR, 256, SMEM_PAIR>>>(out);
    }
}

// round 9
// speedup vs baseline: 1.0571x; 1.0571x over previous
#include <cuda_runtime.h>
#include <cstdint>

#define NN 65536       // nodes (2*B*S)
#define EE 524288      // edges (2*B*EPG)
#define NG 512         // graphs, 128 nodes + 1024 edges each
#define NPAIR 256

// ---------------- device scratch (static: no cudaMalloc allowed) ----------------
__device__ __align__(256) float d_hs[(size_t)NN * 128];     // [:, :64]=h, [:,64:]=store
__device__ __align__(256) float d_g[(size_t)NN * 128];      // relu hidden of comb-MLP
__device__ __align__(256) float d_cR[(size_t)NN * 200];     // [:,0:64]=comb,[:,64:192]=agg,[:,192:200]=0
__device__ __align__(256) float d_pApB[(size_t)NN * 256];   // pA|pB, then R|deg|0pad (cols 0..135)
__device__ __align__(256) float d_uh[(size_t)NN * 128];     // relu hidden of u-MLP
__device__ __align__(256) float d_t[(size_t)NN * 32];
__device__ __align__(256) float d_pe[(size_t)EE * 128];     // per-edge bias (incl b_m1), iter-invariant
__device__ __align__(256) float d_eenc[(size_t)EE * 32];    // e_enc
__device__ unsigned d_eidx[EE];                             // packed local from|to
__device__ __align__(256) float d_Wm2e[136 * 128];          // [W_m2(128); b_m2(1); 0(7)]
__device__ __align__(256) float d_Wu1p[200 * 128];          // [W_u1(192); 0(8)]
__device__ __align__(256) float d_Wm1pack[64 * 256];        // [Wm1[0:64] | Wm1[64:128]] packed
__device__ int d_is64;

// ---------------- precise exp/log (fast-math-proof) ----------------
__device__ __forceinline__ float expp(float x) {
    x = fmaxf(x, -87.0f);
    float nf = rintf(x * 1.4426950408889634f);
    float r = fmaf(nf, -0.693145751953125f, x);     // ln2_hi
    r = fmaf(nf, -1.428606765330187e-6f, r);        // ln2_lo
    float p = 1.9841269841e-4f;
    p = fmaf(p, r, 1.3888888889e-3f);
    p = fmaf(p, r, 8.3333333333e-3f);
    p = fmaf(p, r, 4.1666666667e-2f);
    p = fmaf(p, r, 1.6666666667e-1f);
    p = fmaf(p, r, 0.5f);
    p = fmaf(p, r, 1.0f);
    p = fmaf(p, r, 1.0f);
    int n = (int)nf;
    return p * __int_as_float((n + 127) << 23);
}

__device__ __forceinline__ float logp(float x) {
    int i = __float_as_int(x);
    int e = (i - 0x3f3504f3) >> 23;
    float m = __int_as_float(i - (e << 23));
    float f = m - 1.0f;
    float s = __fdiv_rn(f, 2.0f + f);
    float s2 = s * s;
    float p = 0.2222222222f;
    p = fmaf(p, s2, 0.2857142857f);
    p = fmaf(p, s2, 0.4f);
    p = fmaf(p, s2, 0.6666666667f);
    p = fmaf(p, s2, 2.0f);
    float lm = s * p;
    float ef = (float)e;
    float r = fmaf(ef, 1.428606765330187e-6f, lm);
    r = fmaf(ef, 0.693145751953125f, r);
    return r;
}

// ---------------- index dtype detection + conversion ----------------
__global__ void detect_kernel(const unsigned* __restrict__ p) {
    if (threadIdx.x == 0) {
        int is64 = 1;
        for (int i = 1; i < 64; i += 2)
            if (p[i] != 0u) { is64 = 0; break; }
        d_is64 = is64;
    }
}

__global__ void convert_kernel(const void* __restrict__ fr, const void* __restrict__ to) {
    int e = blockIdx.x * 256 + threadIdx.x;
    if (e >= EE) return;
    int f, t;
    if (d_is64) {
        f = (int)((const long long*)fr)[e];
        t = (int)((const long long*)to)[e];
    } else {
        f = ((const int*)fr)[e];
        t = ((const int*)to)[e];
    }
    d_eidx[e] = (unsigned)(f & 127) | (((unsigned)(t & 127)) << 8);
}

// zero store-half of hs and pad columns of cR
__global__ void init_kernel() {
    int i = blockIdx.x * 256 + threadIdx.x;
    if (i < NN * 64) d_hs[((size_t)(i >> 6)) * 128 + 64 + (i & 63)] = 0.f;
    if (i < NN * 8)  d_cR[((size_t)(i >> 3)) * 200 + 192 + (i & 7)] = 0.f;
}

// ---------------- weight padding/packing precompute (pure copies, exact) ----------------
__global__ void precompute_kernel(
    const float* __restrict__ Wm2, const float* __restrict__ bm2,
    const float* __restrict__ Wu1, const float* __restrict__ Wm1)
{
    int idx = blockIdx.x * 256 + threadIdx.x;
    if (idx < 136 * 128) {
        int r = idx >> 7, j = idx & 127;
        float v = 0.f;
        if (r < 128) v = Wm2[r * 128 + j];
        else if (r == 128) v = bm2[j];
        d_Wm2e[idx] = v;
        return;
    }
    idx -= 136 * 128;
    if (idx < 200 * 128) {
        int r = idx >> 7;
        d_Wu1p[idx] = (r < 192) ? Wu1[idx] : 0.f;
        return;
    }
    idx -= 200 * 128;
    if (idx < 64 * 256) {
        int k = idx >> 8, j = idx & 255;
        d_Wm1pack[idx] = (j < 128) ? Wm1[k * 128 + j] : Wm1[(64 + k) * 128 + (j - 128)];
    }
}

// ---------------- eenc: e_enc = edge_f(Ex8) @ W_enc_e(8x32) + b, ascending-k ----------------
__global__ void __launch_bounds__(256) eenc_kernel(
    const float* __restrict__ ef, const float* __restrict__ W, const float* __restrict__ b)
{
    __shared__ float sW[8 * 32], sb[32], sf[64 * 8];
    const int tid = threadIdx.x;
    if (tid < 256) sW[tid] = W[tid];
    if (tid < 32) sb[tid] = b[tid];
    const size_t base = (size_t)blockIdx.x * 64;
    if (tid < 128) ((float4*)sf)[tid] = ((const float4*)(ef + base * 8))[tid];
    __syncthreads();

    const int e_loc = tid >> 2;
    const int jq = (tid & 3) * 8;
    float f[8];
#pragma unroll
    for (int k = 0; k < 8; k++) f[k] = sf[e_loc * 8 + k];
    float o[8];
#pragma unroll
    for (int j = 0; j < 8; j++) {
        float s = 0.f;
#pragma unroll
        for (int k = 0; k < 8; k++) s += f[k] * sW[k * 32 + jq + j];
        o[j] = s + sb[jq + j];
    }
    float* dst = d_eenc + (base + e_loc) * 32 + jq;
    *(float4*)dst = make_float4(o[0], o[1], o[2], o[3]);
    *(float4*)(dst + 4) = make_float4(o[4], o[5], o[6], o[7]);
}

// ---------------- SGEMM v3 (8-deep, double-buffered) templated on BN in {128,64} ----------------
// C = [relu](A(rows x K) @ B(K x M) + bias); rows mult 128, K mult 8, lda/ldb/ldc/M mult 4.
template<int BN>
__global__ void __launch_bounds__(256) sgemm_kernel(
    const float* __restrict__ A, int lda,
    const float* __restrict__ B, int ldb,
    float* __restrict__ C, int ldc,
    const float* __restrict__ bias,
    int K, int M, int doRelu)
{
    __shared__ __align__(16) float As[2][8][128];
    __shared__ __align__(16) float Bs[2][8][BN];
    const int tid = threadIdx.x;
    const int tx = tid & 15, ty = tid >> 4;
    const int brow = blockIdx.y << 7;
    const int bcol = blockIdx.x * BN;
    const int arow = tid >> 1;
    const int akq  = (tid & 1) << 2;
    // B loader: BN=128 -> all 256 threads; BN=64 -> first 128 threads
    const int bkr  = (BN == 128) ? (tid >> 5) : (tid >> 4);
    const int bcq  = (BN == 128) ? ((tid & 31) << 2) : ((tid & 15) << 2);
    const int bc   = bcol + bcq;
    const bool bload = (BN == 128) || (tid < 128);

    constexpr int NJ = (BN == 128) ? 8 : 4;
    float acc[8][NJ];
#pragma unroll
    for (int i = 0; i < 8; i++)
#pragma unroll
        for (int j = 0; j < NJ; j++) acc[i][j] = 0.f;

    // prologue: tile 0
    {
        float4 av = *reinterpret_cast<const float4*>(A + (size_t)(brow + arow) * lda + akq);
        As[0][akq + 0][arow] = av.x; As[0][akq + 1][arow] = av.y;
        As[0][akq + 2][arow] = av.z; As[0][akq + 3][arow] = av.w;
        if (bload) {
            float4 bv = make_float4(0.f, 0.f, 0.f, 0.f);
            if (bc < M) bv = *reinterpret_cast<const float4*>(B + (size_t)bkr * ldb + bc);
            *reinterpret_cast<float4*>(&Bs[0][bkr][bcq]) = bv;
        }
    }
    __syncthreads();

    int buf = 0;
    for (int k0 = 0; k0 < K; k0 += 8) {
        float4 av, bv;
        const bool more = (k0 + 8 < K);
        if (more) {
            av = *reinterpret_cast<const float4*>(A + (size_t)(brow + arow) * lda + k0 + 8 + akq);
            if (bload) {
                bv = make_float4(0.f, 0.f, 0.f, 0.f);
                if (bc < M) bv = *reinterpret_cast<const float4*>(B + (size_t)(k0 + 8 + bkr) * ldb + bc);
            }
        }
#pragma unroll
        for (int kk = 0; kk < 8; kk++) {
            float4 a0 = *reinterpret_cast<const float4*>(&As[buf][kk][ty * 4]);
            float4 a1 = *reinterpret_cast<const float4*>(&As[buf][kk][64 + ty * 4]);
            float a[8] = {a0.x,a0.y,a0.z,a0.w,a1.x,a1.y,a1.z,a1.w};
            float4 b0 = *reinterpret_cast<const float4*>(&Bs[buf][kk][tx * 4]);
            float b[NJ];
            b[0]=b0.x; b[1]=b0.y; b[2]=b0.z; b[3]=b0.w;
            if (BN == 128) {
                float4 b1 = *reinterpret_cast<const float4*>(&Bs[buf][kk][64 + tx * 4]);
                b[4]=b1.x; b[5]=b1.y; b[6]=b1.z; b[7]=b1.w;
            }
#pragma unroll
            for (int i = 0; i < 8; i++)
#pragma unroll
                for (int j = 0; j < NJ; j++) acc[i][j] += a[i] * b[j];
        }
        if (more) {
            int nb = buf ^ 1;
            As[nb][akq + 0][arow] = av.x; As[nb][akq + 1][arow] = av.y;
            As[nb][akq + 2][arow] = av.z; As[nb][akq + 3][arow] = av.w;
            if (bload) *reinterpret_cast<float4*>(&Bs[nb][bkr][bcq]) = bv;
            __syncthreads();
            buf = nb;
        }
    }

#pragma unroll
    for (int ri = 0; ri < 2; ri++) {
#pragma unroll
        for (int i = 0; i < 4; i++) {
            int row = brow + ri * 64 + ty * 4 + i;
            int ai = ri * 4 + i;
#pragma unroll
            for (int cj = 0; cj < NJ / 4; cj++) {
                int col = bcol + cj * 64 + tx * 4;
                if (col < M) {
                    int aj = cj * 4;
                    float4 v = make_float4(acc[ai][aj], acc[ai][aj+1], acc[ai][aj+2], acc[ai][aj+3]);
                    if (bias) {
                        v.x += bias[col]; v.y += bias[col+1];
                        v.z += bias[col+2]; v.w += bias[col+3];
                    }
                    if (doRelu) {
                        v.x = fmaxf(v.x, 0.f); v.y = fmaxf(v.y, 0.f);
                        v.z = fmaxf(v.z, 0.f); v.w = fmaxf(v.w, 0.f);
                    }
                    *reinterpret_cast<float4*>(C + (size_t)row * ldc + col) = v;
                }
            }
        }
    }
}

// ---------------- fused t-MLP ----------------
__global__ void __launch_bounds__(256) tmlp_kernel(
    const float* __restrict__ Wt1, const float* __restrict__ bt1,
    const float* __restrict__ Wt2, const float* __restrict__ bt2)
{
    __shared__ float sW1[64 * 32], sW2[32 * 32], sb1[32], sb2[32];
    const int tid = threadIdx.x;
    for (int i = tid; i < 64 * 32; i += 256) sW1[i] = Wt1[i];
    for (int i = tid; i < 32 * 32; i += 256) sW2[i] = Wt2[i];
    if (tid < 32) { sb1[tid] = bt1[tid]; sb2[tid] = bt2[tid]; }
    __syncthreads();

    const size_t row = (size_t)blockIdx.x * 256 + tid;
    float h[64];
    const float4* hp = (const float4*)&d_hs[row * 128];
#pragma unroll
    for (int q = 0; q < 16; q++) {
        float4 v = hp[q];
        h[q*4+0] = v.x; h[q*4+1] = v.y; h[q*4+2] = v.z; h[q*4+3] = v.w;
    }
    float th[32];
#pragma unroll
    for (int j = 0; j < 32; j++) {
        float s = 0.f;
        for (int k = 0; k < 64; k++) s += h[k] * sW1[k * 32 + j];
        th[j] = fmaxf(s + sb1[j], 0.f);
    }
#pragma unroll
    for (int j = 0; j < 32; j++) {
        float s = 0.f;
        for (int k = 0; k < 32; k++) s += th[k] * sW2[k * 32 + j];
        d_t[row * 32 + j] = s + sb2[j];
    }
}

// ---------------- per-graph edge message + aggregate ----------------
__global__ void __launch_bounds__(128) edge_kernel() {
    extern __shared__ float sm[];
    float* sP = sm;                       // 128*256
    float* sR = sm + 128 * 256;           // 128*128
    unsigned* se = (unsigned*)(sR + 128 * 128);  // 1024
    int* sdeg = (int*)(se + 1024);        // 128
    const int g = blockIdx.x;
    const int j = threadIdx.x;

    float* gp = d_pApB + (size_t)g * 128 * 256;
    for (int i = j; i < 128 * 256 / 4; i += 128)
        ((float4*)sP)[i] = ((const float4*)gp)[i];
    for (int i = j; i < 128 * 128 / 4; i += 128)
        ((float4*)sR)[i] = make_float4(0.f, 0.f, 0.f, 0.f);
    for (int e = j; e < 1024; e += 128) se[e] = d_eidx[g * 1024 + e];
    sdeg[j] = 0;
    __syncthreads();

    for (int e = j; e < 1024; e += 128) {
        unsigned v = se[e];
        atomicAdd(&sdeg[v & 255], 1);
        atomicAdd(&sdeg[(v >> 8) & 255], 1);
    }

    const float* peg = d_pe + ((size_t)g * 1024) * 128 + j;
    float pa[8], pb[8];
#pragma unroll
    for (int u = 0; u < 8; u++) pa[u] = peg[(size_t)u * 128];

    for (int eb = 0; eb < 1024; eb += 8) {
        if (eb + 8 < 1024) {
#pragma unroll
            for (int u = 0; u < 8; u++) pb[u] = peg[(size_t)(eb + 8 + u) * 128];
        }
#pragma unroll
        for (int u = 0; u < 8; u++) {
            unsigned v = se[eb + u];
            int f = v & 255, t = (v >> 8) & 255;
            float p = pa[u];
            float zf = sP[f * 256 + j] + sP[t * 256 + 128 + j] + p;
            float zr = sP[t * 256 + j] + sP[f * 256 + 128 + j] + p;
            sR[t * 128 + j] += fmaxf(zf, 0.f);
            sR[f * 128 + j] += fmaxf(zr, 0.f);
        }
#pragma unroll
        for (int u = 0; u < 8; u++) pa[u] = pb[u];
    }
    __syncthreads();
    for (int r = 0; r < 128; r++)
        gp[(size_t)r * 256 + j] = sR[r * 128 + j];
    if (j < 8) {
        for (int r = 0; r < 128; r++)
            gp[(size_t)r * 256 + 128 + j] = (j == 0) ? (float)sdeg[r] : 0.f;
    }
}

// ---------------- per-pair: 101 KB smem, 2 CTAs/SM, phased buffer reuse ----------------
__global__ void __launch_bounds__(256, 2) pair_kernel(float* __restrict__ out) {
    extern __shared__ float sm[];
    float* A   = sm;                // 128*129 = 16512
    float* buf = A + 16512;         // 8192
    float* pm  = buf + 8192;        // 256
    float* ps  = pm + 256;          // 256
    float* f   = ps + 256;          // 128
    const int p = blockIdx.x;
    const int tid = threadIdx.x;
    const int r = tid & 127;
    const int half = tid >> 7;
    const int c0 = half << 6;
    const size_t qbase = (size_t)(2 * p) * 128;
    const size_t cbase = (size_t)(2 * p + 1) * 128;

    float tq[32];
#pragma unroll
    for (int k = 0; k < 32; k++) tq[k] = d_t[(qbase + r) * 32 + k];
    for (int idx = tid; idx < 128 * 32 / 4; idx += 256)
        ((float4*)buf)[idx] = ((const float4*)(d_t + cbase * 32))[idx];
    __syncthreads();

    for (int jj = c0; jj < c0 + 64; jj++) {
        float s = 0.f;
        const float4* tc4 = (const float4*)(buf + jj * 32);
#pragma unroll
        for (int q = 0; q < 8; q++) {
            float4 cv = tc4[q];
            s += tq[q*4+0] * cv.x; s += tq[q*4+1] * cv.y;
            s += tq[q*4+2] * cv.z; s += tq[q*4+3] * cv.w;
        }
        A[r * 129 + jj] = __fdiv_rn(s, 0.1f);
    }
    __syncthreads();

    for (int it = 0; it < 20; it++) {
        float m = -1e30f;
        for (int jj = c0; jj < c0 + 64; jj++) m = fmaxf(m, A[r * 129 + jj]);
        pm[half * 128 + r] = m;
        __syncthreads();
        float M2 = fmaxf(pm[r], pm[128 + r]);
        float s = 0.f;
        for (int jj = c0; jj < c0 + 64; jj++) s += expp(A[r * 129 + jj] - M2);
        ps[half * 128 + r] = s;
        __syncthreads();
        float l = M2 + logp(ps[r] + ps[128 + r]);
        for (int jj = c0; jj < c0 + 64; jj++) A[r * 129 + jj] -= l;
        __syncthreads();
        m = -1e30f;
        for (int ii = c0; ii < c0 + 64; ii++) m = fmaxf(m, A[ii * 129 + r]);
        pm[half * 128 + r] = m;
        __syncthreads();
        M2 = fmaxf(pm[r], pm[128 + r]);
        s = 0.f;
        for (int ii = c0; ii < c0 + 64; ii++) s += expp(A[ii * 129 + r] - M2);
        ps[half * 128 + r] = s;
        __syncthreads();
        l = M2 + logp(ps[r] + ps[128 + r]);
        for (int ii = c0; ii < c0 + 64; ii++) A[ii * 129 + r] -= l;
        __syncthreads();
    }

    for (int jj = c0; jj < c0 + 64; jj++)
        A[r * 129 + jj] = expp(A[r * 129 + jj]);
    for (int idx = tid; idx < 128 * 64 / 4; idx += 256) {
        int rr = idx >> 4, c4 = (idx & 15) << 2;
        ((float4*)buf)[idx] = *(const float4*)&d_hs[(cbase + rr) * 128 + c4];
    }
    __syncthreads();

    const int d0 = half << 5;
    float acc[32];
#pragma unroll
    for (int d = 0; d < 32; d++) acc[d] = 0.f;
    for (int jj = 0; jj < 128; jj++) {
        float t = A[r * 129 + jj];
        const float4* cv4 = (const float4*)(buf + jj * 64 + d0);
#pragma unroll
        for (int q = 0; q < 8; q++) {
            float4 cv = cv4[q];
            acc[q*4+0] += t * cv.x; acc[q*4+1] += t * cv.y;
            acc[q*4+2] += t * cv.z; acc[q*4+3] += t * cv.w;
        }
    }
    float sloc = 0.f;
    {
        const float4* qp = (const float4*)&d_hs[(qbase + r) * 128 + d0];
#pragma unroll
        for (int q8 = 0; q8 < 8; q8++) {
            float4 qv = qp[q8];
            sloc += fmaxf(qv.x - acc[q8*4+0], 0.f);
            sloc += fmaxf(qv.y - acc[q8*4+1], 0.f);
            sloc += fmaxf(qv.z - acc[q8*4+2], 0.f);
            sloc += fmaxf(qv.w - acc[q8*4+3], 0.f);
        }
    }
#pragma unroll
    for (int d = 0; d < 32; d++)
        d_hs[(qbase + r) * 128 + 64 + d0 + d] = acc[d];
    ps[half * 128 + r] = sloc;
    __syncthreads();

    for (int idx = tid; idx < 128 * 64 / 4; idx += 256) {
        int rr = idx >> 4, c4 = (idx & 15) << 2;
        ((float4*)buf)[idx] = *(const float4*)&d_hs[(qbase + rr) * 128 + c4];
    }
    if (tid < 128) f[tid] = ps[tid] + ps[128 + tid];
    __syncthreads();

    if (tid < 32) {
        float v = f[tid] + f[tid + 32] + f[tid + 64] + f[tid + 96];
#pragma unroll
        for (int o = 16; o; o >>= 1) v += __shfl_down_sync(0xffffffffu, v, o);
        if (tid == 0) out[p] = -v;
    }

#pragma unroll
    for (int d = 0; d < 32; d++) acc[d] = 0.f;
    for (int ii = 0; ii < 128; ii++) {
        float t = A[ii * 129 + r];
        const float4* qv4 = (const float4*)(buf + ii * 64 + d0);
#pragma unroll
        for (int q = 0; q < 8; q++) {
            float4 qv = qv4[q];
            acc[q*4+0] += t * qv.x; acc[q*4+1] += t * qv.y;
            acc[q*4+2] += t * qv.z; acc[q*4+3] += t * qv.w;
        }
    }
#pragma unroll
    for (int d = 0; d < 32; d++)
        d_hs[(cbase + r) * 128 + 64 + d0 + d] = acc[d];
}

// ---------------- launcher ----------------
static void run_sgemm(const float* A, int lda, const float* B, int ldb,
                      float* C, int ldc, const float* bias,
                      int rows, int K, int M, int relu) {
    if (M <= 64) {
        dim3 grid(1, rows / 128);
        sgemm_kernel<64><<<grid, 256>>>(A, lda, B, ldb, C, ldc, bias, K, M, relu);
    } else {
        dim3 grid((M + 127) / 128, rows / 128);
        sgemm_kernel<128><<<grid, 256>>>(A, lda, B, ldb, C, ldc, bias, K, M, relu);
    }
}

extern "C" void kernel_launch(void* const* d_in, const int* in_sizes, int n_in,
                              void* d_out, int out_size) {
    const float* node_f = (const float*)d_in[0];
    const float* edge_f = (const float*)d_in[1];
    const float* W_enc_n = (const float*)d_in[2];
    const float* b_enc_n = (const float*)d_in[3];
    const float* W_enc_e = (const float*)d_in[4];
    const float* b_enc_e = (const float*)d_in[5];
    const float* W_c1 = (const float*)d_in[6];
    const float* b_c1 = (const float*)d_in[7];
    const float* W_c2 = (const float*)d_in[8];
    const float* b_c2 = (const float*)d_in[9];
    const float* W_m1 = (const float*)d_in[10];
    const float* b_m1 = (const float*)d_in[11];
    const float* W_m2 = (const float*)d_in[12];
    const float* b_m2 = (const float*)d_in[13];
    const float* W_u1 = (const float*)d_in[14];
    const float* b_u1 = (const float*)d_in[15];
    const float* W_u2 = (const float*)d_in[16];
    const float* b_u2 = (const float*)d_in[17];
    const float* W_t1 = (const float*)d_in[18];
    const float* b_t1 = (const float*)d_in[19];
    const float* W_t2 = (const float*)d_in[20];
    const float* b_t2 = (const float*)d_in[21];
    const void* from_idx = d_in[22];
    const void* to_idx = d_in[23];
    float* out = (float*)d_out;

    static const int SMEM_EDGE = (128 * 256 + 128 * 128) * 4 + 1024 * 4 + 128 * 4; // 201216
    static const int SMEM_PAIR = (16512 + 8192 + 256 + 256 + 128) * 4;             // 101376
    cudaFuncSetAttribute(edge_kernel, cudaFuncAttributeMaxDynamicSharedMemorySize, SMEM_EDGE);
    cudaFuncSetAttribute(pair_kernel, cudaFuncAttributeMaxDynamicSharedMemorySize, SMEM_PAIR);

    float* hs; cudaGetSymbolAddress((void**)&hs, d_hs);
    float* gbuf; cudaGetSymbolAddress((void**)&gbuf, d_g);
    float* cR; cudaGetSymbolAddress((void**)&cR, d_cR);
    float* pApB; cudaGetSymbolAddress((void**)&pApB, d_pApB);
    float* uh; cudaGetSymbolAddress((void**)&uh, d_uh);
    float* pe; cudaGetSymbolAddress((void**)&pe, d_pe);
    float* eenc; cudaGetSymbolAddress((void**)&eenc, d_eenc);
    float* Wm2e; cudaGetSymbolAddress((void**)&Wm2e, d_Wm2e);
    float* Wu1p; cudaGetSymbolAddress((void**)&Wu1p, d_Wu1p);
    float* Wm1pack; cudaGetSymbolAddress((void**)&Wm1pack, d_Wm1pack);

    // setup — pe SGEMM stays at launch index 3 (profiled)
    detect_kernel<<<1, 32>>>((const unsigned*)from_idx);                         // 0
    convert_kernel<<<EE / 256, 256>>>(from_idx, to_idx);                         // 1
    eenc_kernel<<<EE / 64, 256>>>(edge_f, W_enc_e, b_enc_e);                     // 2
    run_sgemm(eenc, 32, W_m1 + 128 * 128, 128, pe, 128, b_m1, EE, 32, 128, 0);   // 3
    init_kernel<<<(NN * 64) / 256, 256>>>();                                     // 4
    precompute_kernel<<<(136 * 128 + 200 * 128 + 64 * 256 + 255) / 256, 256>>>(
        W_m2, b_m2, W_u1, W_m1);                                                 // 5
    run_sgemm(node_f, 16, W_enc_n, 64, hs, 128, b_enc_n, NN, 16, 64, 0);         // 6

    for (int iter = 0; iter < 5; iter++) {
        // g = relu([h|store] @ W_c1 + b_c1)
        run_sgemm(hs, 128, W_c1, 128, gbuf, 128, b_c1, NN, 128, 128, 1);
        // comb = g @ W_c2 + b_c2  -> cR[:, 0:64]
        run_sgemm(gbuf, 128, W_c2, 64, cR, 200, b_c2, NN, 128, 64, 0);
        // pA|pB = comb @ Wm1pack  (M=256)
        run_sgemm(cR, 200, Wm1pack, 256, pApB, 256, nullptr, NN, 64, 256, 0);
        // R|deg -> pApB cols 0..135
        edge_kernel<<<NG, 128, SMEM_EDGE>>>();
        // agg = [R|deg|0] @ Wm2e -> cR[:, 64:192]
        run_sgemm(pApB, 256, Wm2e, 128, cR + 64, 200, nullptr, NN, 136, 128, 0);
        // uh = relu([comb|agg] @ Wu1p + b_u1)
        run_sgemm(cR, 200, Wu1p, 128, uh, 128, b_u1, NN, 200, 128, 1);
        // h = uh @ W_u2 + b_u2 -> hs[:, :64]
        run_sgemm(uh, 128, W_u2, 64, hs, 128, b_u2, NN, 128, 64, 0);
        // t = relu(h @ W_t1 + b_t1) @ W_t2 + b_t2 (fused)
        tmlp_kernel<<<NN / 256, 256>>>(W_t1, b_t1, W_t2, b_t2);
        // sinkhorn + transports + store + scores
        pair_kernel<<<NPAIR, 256, SMEM_PAIR>>>(out);
    }
}

// round 10
// speedup vs baseline: 1.0654x; 1.0078x over previous
#include <cuda_runtime.h>
#include <cstdint>

#define NN 65536       // nodes (2*B*S)
#define EE 524288      // edges (2*B*EPG)
#define NG 512         // graphs, 128 nodes + 1024 edges each
#define NPAIR 256

// ---------------- device scratch (static: no cudaMalloc allowed) ----------------
__device__ __align__(256) float d_hs[(size_t)NN * 128];     // [:, :64]=h, [:,64:]=store
__device__ __align__(256) float d_g[(size_t)NN * 128];      // relu hidden of comb-MLP
__device__ __align__(256) float d_cR[(size_t)NN * 200];     // [:,0:64]=comb,[:,64:192]=agg,[:,192:200]=0
__device__ __align__(256) float d_pApB[(size_t)NN * 256];   // pA|pB, then R|deg|0pad (cols 0..135)
__device__ __align__(256) float d_uh[(size_t)NN * 128];     // relu hidden of u-MLP
__device__ __align__(256) float d_t[(size_t)NN * 32];
__device__ __align__(256) float d_pe[(size_t)EE * 128];     // per-edge bias (incl b_m1), iter-invariant
__device__ __align__(256) float d_eenc[(size_t)EE * 32];    // e_enc
__device__ unsigned d_eidx[EE];                             // packed local from|to
__device__ __align__(256) float d_Wm2e[136 * 128];          // [W_m2(128); b_m2(1); 0(7)]
__device__ __align__(256) float d_Wu1p[200 * 128];          // [W_u1(192); 0(8)]
__device__ __align__(256) float d_Wm1pack[64 * 256];        // [Wm1[0:64] | Wm1[64:128]] packed
__device__ int d_is64;

// ---------------- index dtype detection + conversion ----------------
__global__ void detect_kernel(const unsigned* __restrict__ p) {
    if (threadIdx.x == 0) {
        int is64 = 1;
        for (int i = 1; i < 64; i += 2)
            if (p[i] != 0u) { is64 = 0; break; }
        d_is64 = is64;
    }
}

__global__ void convert_kernel(const void* __restrict__ fr, const void* __restrict__ to) {
    int e = blockIdx.x * 256 + threadIdx.x;
    if (e >= EE) return;
    int f, t;
    if (d_is64) {
        f = (int)((const long long*)fr)[e];
        t = (int)((const long long*)to)[e];
    } else {
        f = ((const int*)fr)[e];
        t = ((const int*)to)[e];
    }
    d_eidx[e] = (unsigned)(f & 127) | (((unsigned)(t & 127)) << 8);
}

// zero store-half of hs and pad columns of cR
__global__ void init_kernel() {
    int i = blockIdx.x * 256 + threadIdx.x;
    if (i < NN * 64) d_hs[((size_t)(i >> 6)) * 128 + 64 + (i & 63)] = 0.f;
    if (i < NN * 8)  d_cR[((size_t)(i >> 3)) * 200 + 192 + (i & 7)] = 0.f;
}

// ---------------- weight padding/packing precompute (pure copies, exact) ----------------
__global__ void precompute_kernel(
    const float* __restrict__ Wm2, const float* __restrict__ bm2,
    const float* __restrict__ Wu1, const float* __restrict__ Wm1)
{
    int idx = blockIdx.x * 256 + threadIdx.x;
    if (idx < 136 * 128) {
        int r = idx >> 7, j = idx & 127;
        float v = 0.f;
        if (r < 128) v = Wm2[r * 128 + j];
        else if (r == 128) v = bm2[j];
        d_Wm2e[idx] = v;
        return;
    }
    idx -= 136 * 128;
    if (idx < 200 * 128) {
        int r = idx >> 7;
        d_Wu1p[idx] = (r < 192) ? Wu1[idx] : 0.f;
        return;
    }
    idx -= 200 * 128;
    if (idx < 64 * 256) {
        int k = idx >> 8, j = idx & 255;
        d_Wm1pack[idx] = (j < 128) ? Wm1[k * 128 + j] : Wm1[(64 + k) * 128 + (j - 128)];
    }
}

// ---------------- eenc: e_enc = edge_f(Ex8) @ W_enc_e(8x32) + b, ascending-k ----------------
__global__ void __launch_bounds__(256) eenc_kernel(
    const float* __restrict__ ef, const float* __restrict__ W, const float* __restrict__ b)
{
    __shared__ float sW[8 * 32], sb[32], sf[64 * 8];
    const int tid = threadIdx.x;
    if (tid < 256) sW[tid] = W[tid];
    if (tid < 32) sb[tid] = b[tid];
    const size_t base = (size_t)blockIdx.x * 64;
    if (tid < 128) ((float4*)sf)[tid] = ((const float4*)(ef + base * 8))[tid];
    __syncthreads();

    const int e_loc = tid >> 2;
    const int jq = (tid & 3) * 8;
    float f[8];
#pragma unroll
    for (int k = 0; k < 8; k++) f[k] = sf[e_loc * 8 + k];
    float o[8];
#pragma unroll
    for (int j = 0; j < 8; j++) {
        float s = 0.f;
#pragma unroll
        for (int k = 0; k < 8; k++) s += f[k] * sW[k * 32 + jq + j];
        o[j] = s + sb[jq + j];
    }
    float* dst = d_eenc + (base + e_loc) * 32 + jq;
    *(float4*)dst = make_float4(o[0], o[1], o[2], o[3]);
    *(float4*)(dst + 4) = make_float4(o[4], o[5], o[6], o[7]);
}

// ---------------- SGEMM v3 (8-deep, double-buffered) templated on BN in {128,64} ----------------
template<int BN>
__global__ void __launch_bounds__(256) sgemm_kernel(
    const float* __restrict__ A, int lda,
    const float* __restrict__ B, int ldb,
    float* __restrict__ C, int ldc,
    const float* __restrict__ bias,
    int K, int M, int doRelu)
{
    __shared__ __align__(16) float As[2][8][128];
    __shared__ __align__(16) float Bs[2][8][BN];
    const int tid = threadIdx.x;
    const int tx = tid & 15, ty = tid >> 4;
    const int brow = blockIdx.y << 7;
    const int bcol = blockIdx.x * BN;
    const int arow = tid >> 1;
    const int akq  = (tid & 1) << 2;
    const int bkr  = (BN == 128) ? (tid >> 5) : (tid >> 4);
    const int bcq  = (BN == 128) ? ((tid & 31) << 2) : ((tid & 15) << 2);
    const int bc   = bcol + bcq;
    const bool bload = (BN == 128) || (tid < 128);

    constexpr int NJ = (BN == 128) ? 8 : 4;
    float acc[8][NJ];
#pragma unroll
    for (int i = 0; i < 8; i++)
#pragma unroll
        for (int j = 0; j < NJ; j++) acc[i][j] = 0.f;

    {
        float4 av = *reinterpret_cast<const float4*>(A + (size_t)(brow + arow) * lda + akq);
        As[0][akq + 0][arow] = av.x; As[0][akq + 1][arow] = av.y;
        As[0][akq + 2][arow] = av.z; As[0][akq + 3][arow] = av.w;
        if (bload) {
            float4 bv = make_float4(0.f, 0.f, 0.f, 0.f);
            if (bc < M) bv = *reinterpret_cast<const float4*>(B + (size_t)bkr * ldb + bc);
            *reinterpret_cast<float4*>(&Bs[0][bkr][bcq]) = bv;
        }
    }
    __syncthreads();

    int buf = 0;
    for (int k0 = 0; k0 < K; k0 += 8) {
        float4 av, bv;
        const bool more = (k0 + 8 < K);
        if (more) {
            av = *reinterpret_cast<const float4*>(A + (size_t)(brow + arow) * lda + k0 + 8 + akq);
            if (bload) {
                bv = make_float4(0.f, 0.f, 0.f, 0.f);
                if (bc < M) bv = *reinterpret_cast<const float4*>(B + (size_t)(k0 + 8 + bkr) * ldb + bc);
            }
        }
#pragma unroll
        for (int kk = 0; kk < 8; kk++) {
            float4 a0 = *reinterpret_cast<const float4*>(&As[buf][kk][ty * 4]);
            float4 a1 = *reinterpret_cast<const float4*>(&As[buf][kk][64 + ty * 4]);
            float a[8] = {a0.x,a0.y,a0.z,a0.w,a1.x,a1.y,a1.z,a1.w};
            float4 b0 = *reinterpret_cast<const float4*>(&Bs[buf][kk][tx * 4]);
            float b[NJ];
            b[0]=b0.x; b[1]=b0.y; b[2]=b0.z; b[3]=b0.w;
            if (BN == 128) {
                float4 b1 = *reinterpret_cast<const float4*>(&Bs[buf][kk][64 + tx * 4]);
                b[4]=b1.x; b[5]=b1.y; b[6]=b1.z; b[7]=b1.w;
            }
#pragma unroll
            for (int i = 0; i < 8; i++)
#pragma unroll
                for (int j = 0; j < NJ; j++) acc[i][j] += a[i] * b[j];
        }
        if (more) {
            int nb = buf ^ 1;
            As[nb][akq + 0][arow] = av.x; As[nb][akq + 1][arow] = av.y;
            As[nb][akq + 2][arow] = av.z; As[nb][akq + 3][arow] = av.w;
            if (bload) *reinterpret_cast<float4*>(&Bs[nb][bkr][bcq]) = bv;
            __syncthreads();
            buf = nb;
        }
    }

#pragma unroll
    for (int ri = 0; ri < 2; ri++) {
#pragma unroll
        for (int i = 0; i < 4; i++) {
            int row = brow + ri * 64 + ty * 4 + i;
            int ai = ri * 4 + i;
#pragma unroll
            for (int cj = 0; cj < NJ / 4; cj++) {
                int col = bcol + cj * 64 + tx * 4;
                if (col < M) {
                    int aj = cj * 4;
                    float4 v = make_float4(acc[ai][aj], acc[ai][aj+1], acc[ai][aj+2], acc[ai][aj+3]);
                    if (bias) {
                        v.x += bias[col]; v.y += bias[col+1];
                        v.z += bias[col+2]; v.w += bias[col+3];
                    }
                    if (doRelu) {
                        v.x = fmaxf(v.x, 0.f); v.y = fmaxf(v.y, 0.f);
                        v.z = fmaxf(v.z, 0.f); v.w = fmaxf(v.w, 0.f);
                    }
                    *reinterpret_cast<float4*>(C + (size_t)row * ldc + col) = v;
                }
            }
        }
    }
}

// ---------------- fused t-MLP ----------------
__global__ void __launch_bounds__(256) tmlp_kernel(
    const float* __restrict__ Wt1, const float* __restrict__ bt1,
    const float* __restrict__ Wt2, const float* __restrict__ bt2)
{
    __shared__ float sW1[64 * 32], sW2[32 * 32], sb1[32], sb2[32];
    const int tid = threadIdx.x;
    for (int i = tid; i < 64 * 32; i += 256) sW1[i] = Wt1[i];
    for (int i = tid; i < 32 * 32; i += 256) sW2[i] = Wt2[i];
    if (tid < 32) { sb1[tid] = bt1[tid]; sb2[tid] = bt2[tid]; }
    __syncthreads();

    const size_t row = (size_t)blockIdx.x * 256 + tid;
    float h[64];
    const float4* hp = (const float4*)&d_hs[row * 128];
#pragma unroll
    for (int q = 0; q < 16; q++) {
        float4 v = hp[q];
        h[q*4+0] = v.x; h[q*4+1] = v.y; h[q*4+2] = v.z; h[q*4+3] = v.w;
    }
    float th[32];
#pragma unroll
    for (int j = 0; j < 32; j++) {
        float s = 0.f;
        for (int k = 0; k < 64; k++) s += h[k] * sW1[k * 32 + j];
        th[j] = fmaxf(s + sb1[j], 0.f);
    }
#pragma unroll
    for (int j = 0; j < 32; j++) {
        float s = 0.f;
        for (int k = 0; k < 32; k++) s += th[k] * sW2[k * 32 + j];
        d_t[row * 32 + j] = s + sb2[j];
    }
}

// ---------------- per-graph edge message + aggregate ----------------
__global__ void __launch_bounds__(128) edge_kernel() {
    extern __shared__ float sm[];
    float* sP = sm;                       // 128*256
    float* sR = sm + 128 * 256;           // 128*128
    unsigned* se = (unsigned*)(sR + 128 * 128);  // 1024
    int* sdeg = (int*)(se + 1024);        // 128
    const int g = blockIdx.x;
    const int j = threadIdx.x;

    float* gp = d_pApB + (size_t)g * 128 * 256;
    for (int i = j; i < 128 * 256 / 4; i += 128)
        ((float4*)sP)[i] = ((const float4*)gp)[i];
    for (int i = j; i < 128 * 128 / 4; i += 128)
        ((float4*)sR)[i] = make_float4(0.f, 0.f, 0.f, 0.f);
    for (int e = j; e < 1024; e += 128) se[e] = d_eidx[g * 1024 + e];
    sdeg[j] = 0;
    __syncthreads();

    for (int e = j; e < 1024; e += 128) {
        unsigned v = se[e];
        atomicAdd(&sdeg[v & 255], 1);
        atomicAdd(&sdeg[(v >> 8) & 255], 1);
    }

    const float* peg = d_pe + ((size_t)g * 1024) * 128 + j;
    float pa[8], pb[8];
#pragma unroll
    for (int u = 0; u < 8; u++) pa[u] = peg[(size_t)u * 128];

    for (int eb = 0; eb < 1024; eb += 8) {
        if (eb + 8 < 1024) {
#pragma unroll
            for (int u = 0; u < 8; u++) pb[u] = peg[(size_t)(eb + 8 + u) * 128];
        }
#pragma unroll
        for (int u = 0; u < 8; u++) {
            unsigned v = se[eb + u];
            int f = v & 255, t = (v >> 8) & 255;
            float p = pa[u];
            float zf = sP[f * 256 + j] + sP[t * 256 + 128 + j] + p;
            float zr = sP[t * 256 + j] + sP[f * 256 + 128 + j] + p;
            sR[t * 128 + j] += fmaxf(zf, 0.f);
            sR[f * 128 + j] += fmaxf(zr, 0.f);
        }
#pragma unroll
        for (int u = 0; u < 8; u++) pa[u] = pb[u];
    }
    __syncthreads();
    for (int r = 0; r < 128; r++)
        gp[(size_t)r * 256 + j] = sR[r * 128 + j];
    if (j < 8) {
        for (int r = 0; r < 128; r++)
            gp[(size_t)r * 256 + 128 + j] = (j == 0) ? (float)sdeg[r] : 0.f;
    }
}

// ---------------- per-pair: MUFU-based exp/log (this round's experiment) ----------------
__global__ void __launch_bounds__(256, 2) pair_kernel(float* __restrict__ out) {
    extern __shared__ float sm[];
    float* A   = sm;                // 128*129 = 16512
    float* buf = A + 16512;         // 8192
    float* pm  = buf + 8192;        // 256
    float* ps  = pm + 256;          // 256
    float* f   = ps + 256;          // 128
    const int p = blockIdx.x;
    const int tid = threadIdx.x;
    const int r = tid & 127;
    const int half = tid >> 7;
    const int c0 = half << 6;
    const size_t qbase = (size_t)(2 * p) * 128;
    const size_t cbase = (size_t)(2 * p + 1) * 128;

    float tq[32];
#pragma unroll
    for (int k = 0; k < 32; k++) tq[k] = d_t[(qbase + r) * 32 + k];
    for (int idx = tid; idx < 128 * 32 / 4; idx += 256)
        ((float4*)buf)[idx] = ((const float4*)(d_t + cbase * 32))[idx];
    __syncthreads();

    for (int jj = c0; jj < c0 + 64; jj++) {
        float s = 0.f;
        const float4* tc4 = (const float4*)(buf + jj * 32);
#pragma unroll
        for (int q = 0; q < 8; q++) {
            float4 cv = tc4[q];
            s += tq[q*4+0] * cv.x; s += tq[q*4+1] * cv.y;
            s += tq[q*4+2] * cv.z; s += tq[q*4+3] * cv.w;
        }
        A[r * 129 + jj] = __fdiv_rn(s, 0.1f);
    }
    __syncthreads();

    for (int it = 0; it < 20; it++) {
        float m = -1e30f;
        for (int jj = c0; jj < c0 + 64; jj++) m = fmaxf(m, A[r * 129 + jj]);
        pm[half * 128 + r] = m;
        __syncthreads();
        float M2 = fmaxf(pm[r], pm[128 + r]);
        float s = 0.f;
        for (int jj = c0; jj < c0 + 64; jj++) s += __expf(A[r * 129 + jj] - M2);
        ps[half * 128 + r] = s;
        __syncthreads();
        float l = M2 + __logf(ps[r] + ps[128 + r]);
        for (int jj = c0; jj < c0 + 64; jj++) A[r * 129 + jj] -= l;
        __syncthreads();
        m = -1e30f;
        for (int ii = c0; ii < c0 + 64; ii++) m = fmaxf(m, A[ii * 129 + r]);
        pm[half * 128 + r] = m;
        __syncthreads();
        M2 = fmaxf(pm[r], pm[128 + r]);
        s = 0.f;
        for (int ii = c0; ii < c0 + 64; ii++) s += __expf(A[ii * 129 + r] - M2);
        ps[half * 128 + r] = s;
        __syncthreads();
        l = M2 + __logf(ps[r] + ps[128 + r]);
        for (int ii = c0; ii < c0 + 64; ii++) A[ii * 129 + r] -= l;
        __syncthreads();
    }

    for (int jj = c0; jj < c0 + 64; jj++)
        A[r * 129 + jj] = __expf(A[r * 129 + jj]);
    for (int idx = tid; idx < 128 * 64 / 4; idx += 256) {
        int rr = idx >> 4, c4 = (idx & 15) << 2;
        ((float4*)buf)[idx] = *(const float4*)&d_hs[(cbase + rr) * 128 + c4];
    }
    __syncthreads();

    const int d0 = half << 5;
    float acc[32];
#pragma unroll
    for (int d = 0; d < 32; d++) acc[d] = 0.f;
    for (int jj = 0; jj < 128; jj++) {
        float t = A[r * 129 + jj];
        const float4* cv4 = (const float4*)(buf + jj * 64 + d0);
#pragma unroll
        for (int q = 0; q < 8; q++) {
            float4 cv = cv4[q];
            acc[q*4+0] += t * cv.x; acc[q*4+1] += t * cv.y;
            acc[q*4+2] += t * cv.z; acc[q*4+3] += t * cv.w;
        }
    }
    float sloc = 0.f;
    {
        const float4* qp = (const float4*)&d_hs[(qbase + r) * 128 + d0];
#pragma unroll
        for (int q8 = 0; q8 < 8; q8++) {
            float4 qv = qp[q8];
            sloc += fmaxf(qv.x - acc[q8*4+0], 0.f);
            sloc += fmaxf(qv.y - acc[q8*4+1], 0.f);
            sloc += fmaxf(qv.z - acc[q8*4+2], 0.f);
            sloc += fmaxf(qv.w - acc[q8*4+3], 0.f);
        }
    }
#pragma unroll
    for (int d = 0; d < 32; d++)
        d_hs[(qbase + r) * 128 + 64 + d0 + d] = acc[d];
    ps[half * 128 + r] = sloc;
    __syncthreads();

    for (int idx = tid; idx < 128 * 64 / 4; idx += 256) {
        int rr = idx >> 4, c4 = (idx & 15) << 2;
        ((float4*)buf)[idx] = *(const float4*)&d_hs[(qbase + rr) * 128 + c4];
    }
    if (tid < 128) f[tid] = ps[tid] + ps[128 + tid];
    __syncthreads();

    if (tid < 32) {
        float v = f[tid] + f[tid + 32] + f[tid + 64] + f[tid + 96];
#pragma unroll
        for (int o = 16; o; o >>= 1) v += __shfl_down_sync(0xffffffffu, v, o);
        if (tid == 0) out[p] = -v;
    }

#pragma unroll
    for (int d = 0; d < 32; d++) acc[d] = 0.f;
    for (int ii = 0; ii < 128; ii++) {
        float t = A[ii * 129 + r];
        const float4* qv4 = (const float4*)(buf + ii * 64 + d0);
#pragma unroll
        for (int q = 0; q < 8; q++) {
            float4 qv = qv4[q];
            acc[q*4+0] += t * qv.x; acc[q*4+1] += t * qv.y;
            acc[q*4+2] += t * qv.z; acc[q*4+3] += t * qv.w;
        }
    }
#pragma unroll
    for (int d = 0; d < 32; d++)
        d_hs[(cbase + r) * 128 + 64 + d0 + d] = acc[d];
}

// ---------------- launcher ----------------
static void run_sgemm(const float* A, int lda, const float* B, int ldb,
                      float* C, int ldc, const float* bias,
                      int rows, int K, int M, int relu) {
    if (M <= 64) {
        dim3 grid(1, rows / 128);
        sgemm_kernel<64><<<grid, 256>>>(A, lda, B, ldb, C, ldc, bias, K, M, relu);
    } else {
        dim3 grid((M + 127) / 128, rows / 128);
        sgemm_kernel<128><<<grid, 256>>>(A, lda, B, ldb, C, ldc, bias, K, M, relu);
    }
}

extern "C" void kernel_launch(void* const* d_in, const int* in_sizes, int n_in,
                              void* d_out, int out_size) {
    const float* node_f = (const float*)d_in[0];
    const float* edge_f = (const float*)d_in[1];
    const float* W_enc_n = (const float*)d_in[2];
    const float* b_enc_n = (const float*)d_in[3];
    const float* W_enc_e = (const float*)d_in[4];
    const float* b_enc_e = (const float*)d_in[5];
    const float* W_c1 = (const float*)d_in[6];
    const float* b_c1 = (const float*)d_in[7];
    const float* W_c2 = (const float*)d_in[8];
    const float* b_c2 = (const float*)d_in[9];
    const float* W_m1 = (const float*)d_in[10];
    const float* b_m1 = (const float*)d_in[11];
    const float* W_m2 = (const float*)d_in[12];
    const float* b_m2 = (const float*)d_in[13];
    const float* W_u1 = (const float*)d_in[14];
    const float* b_u1 = (const float*)d_in[15];
    const float* W_u2 = (const float*)d_in[16];
    const float* b_u2 = (const float*)d_in[17];
    const float* W_t1 = (const float*)d_in[18];
    const float* b_t1 = (const float*)d_in[19];
    const float* W_t2 = (const float*)d_in[20];
    const float* b_t2 = (const float*)d_in[21];
    const void* from_idx = d_in[22];
    const void* to_idx = d_in[23];
    float* out = (float*)d_out;

    static const int SMEM_EDGE = (128 * 256 + 128 * 128) * 4 + 1024 * 4 + 128 * 4; // 201216
    static const int SMEM_PAIR = (16512 + 8192 + 256 + 256 + 128) * 4;             // 101376
    cudaFuncSetAttribute(edge_kernel, cudaFuncAttributeMaxDynamicSharedMemorySize, SMEM_EDGE);
    cudaFuncSetAttribute(pair_kernel, cudaFuncAttributeMaxDynamicSharedMemorySize, SMEM_PAIR);

    float* hs; cudaGetSymbolAddress((void**)&hs, d_hs);
    float* gbuf; cudaGetSymbolAddress((void**)&gbuf, d_g);
    float* cR; cudaGetSymbolAddress((void**)&cR, d_cR);
    float* pApB; cudaGetSymbolAddress((void**)&pApB, d_pApB);
    float* uh; cudaGetSymbolAddress((void**)&uh, d_uh);
    float* pe; cudaGetSymbolAddress((void**)&pe, d_pe);
    float* eenc; cudaGetSymbolAddress((void**)&eenc, d_eenc);
    float* Wm2e; cudaGetSymbolAddress((void**)&Wm2e, d_Wm2e);
    float* Wu1p; cudaGetSymbolAddress((void**)&Wu1p, d_Wu1p);
    float* Wm1pack; cudaGetSymbolAddress((void**)&Wm1pack, d_Wm1pack);

    // setup — pe SGEMM stays at launch index 3 (profiled)
    detect_kernel<<<1, 32>>>((const unsigned*)from_idx);                         // 0
    convert_kernel<<<EE / 256, 256>>>(from_idx, to_idx);                         // 1
    eenc_kernel<<<EE / 64, 256>>>(edge_f, W_enc_e, b_enc_e);                     // 2
    run_sgemm(eenc, 32, W_m1 + 128 * 128, 128, pe, 128, b_m1, EE, 32, 128, 0);   // 3
    init_kernel<<<(NN * 64) / 256, 256>>>();                                     // 4
    precompute_kernel<<<(136 * 128 + 200 * 128 + 64 * 256 + 255) / 256, 256>>>(
        W_m2, b_m2, W_u1, W_m1);                                                 // 5
    run_sgemm(node_f, 16, W_enc_n, 64, hs, 128, b_enc_n, NN, 16, 64, 0);         // 6

    for (int iter = 0; iter < 5; iter++) {
        run_sgemm(hs, 128, W_c1, 128, gbuf, 128, b_c1, NN, 128, 128, 1);
        run_sgemm(gbuf, 128, W_c2, 64, cR, 200, b_c2, NN, 128, 64, 0);
        run_sgemm(cR, 200, Wm1pack, 256, pApB, 256, nullptr, NN, 64, 256, 0);
        edge_kernel<<<NG, 128, SMEM_EDGE>>>();
        run_sgemm(pApB, 256, Wm2e, 128, cR + 64, 200, nullptr, NN, 136, 128, 0);
        run_sgemm(cR, 200, Wu1p, 128, uh, 128, b_u1, NN, 200, 128, 1);
        run_sgemm(uh, 128, W_u2, 64, hs, 128, b_u2, NN, 128, 64, 0);
        tmlp_kernel<<<NN / 256, 256>>>(W_t1, b_t1, W_t2, b_t2);
        pair_kernel<<<NPAIR, 256, SMEM_PAIR>>>(out);
    }
}